// round 3
// baseline (speedup 1.0000x reference)
#include <cuda_runtime.h>
#include <math.h>

#ifndef M_PI
#define M_PI 3.14159265358979323846
#endif

#define FULLMASK 0xffffffffu

// ---------------- scratch (static device globals; no allocations) ----------------
__device__ float2 g_F[33554432];   // shifted FFT of x_low   (B*C,128,128) complex
__device__ float2 g_G[33554432];   // conv output            (B*C,128,128) complex
__device__ float  g_R[33554432];   // real(ifft2)            (B*C,128,128) float
__device__ float  g_kern[8 * 49];  // per-batch 7x7 kernel
__device__ float  g_Wt[256 * 256]; // refine_w transposed: Wt[c][o] = W[o][c]

// ---------------- complex helpers ----------------
__device__ __forceinline__ float2 cadd(float2 a, float2 b) { return make_float2(a.x + b.x, a.y + b.y); }
__device__ __forceinline__ float2 csub(float2 a, float2 b) { return make_float2(a.x - b.x, a.y - b.y); }
__device__ __forceinline__ float2 cmul(float2 a, float2 b) {
  return make_float2(a.x * b.x - a.y * b.y, a.x * b.y + a.y * b.x);
}

// ---------------- warp-resident 128-pt DIF FFT ----------------
// Lane l holds positions p = s*32 + l, s = 0..3.  Natural input -> bit-reversed output
// (position p holds X[bitrev7(p)]).  SGN = -1 forward, +1 inverse.
template<int SGN>
__device__ __forceinline__ void make_twiddles(int lane, float2 tw[7]) {
  const float TP = 6.283185307179586f * (float)SGN;
  float fr[7] = { lane / 128.f, (lane + 32) / 128.f, lane / 64.f,
                  (lane & 15) / 32.f, (lane & 7) / 16.f, (lane & 3) / 8.f, (lane & 1) / 4.f };
#pragma unroll
  for (int i = 0; i < 7; i++) {
    float s, c;
    sincosf(TP * fr[i], &s, &c);
    tw[i] = make_float2(c, s);
  }
}

__device__ __forceinline__ void fft128(float2 v[4], const float2 tw[7], int lane) {
  float2 t, u;
  // stage half=64 (in-register: s <-> s+2)
  t = v[0]; u = v[2]; v[0] = cadd(t, u); v[2] = cmul(csub(t, u), tw[0]);
  t = v[1]; u = v[3]; v[1] = cadd(t, u); v[3] = cmul(csub(t, u), tw[1]);
  // stage half=32 (in-register: s <-> s+1)
  t = v[0]; u = v[1]; v[0] = cadd(t, u); v[1] = cmul(csub(t, u), tw[2]);
  t = v[2]; u = v[3]; v[2] = cadd(t, u); v[3] = cmul(csub(t, u), tw[2]);
  // stages half=16,8,4,2,1 via shfl_xor
#pragma unroll
  for (int hi = 0; hi < 5; hi++) {
    int h = 16 >> hi;
    bool up = (lane & h) != 0;
#pragma unroll
    for (int s = 0; s < 4; s++) {
      float prx = __shfl_xor_sync(FULLMASK, v[s].x, h);
      float pry = __shfl_xor_sync(FULLMASK, v[s].y, h);
      float2 pr = make_float2(prx, pry);
      if (hi < 4) {
        v[s] = up ? cmul(csub(pr, v[s]), tw[3 + hi]) : cadd(v[s], pr);
      } else {
        v[s] = up ? csub(pr, v[s]) : cadd(v[s], pr);
      }
    }
  }
}

__device__ __forceinline__ int bitrev7(int p) { return (int)(__brev((unsigned)p) >> 25); }

// ---------------- forward FFT: x_low -> g_F (shifted, ortho-normalized) ----------------
__global__ void __launch_bounds__(512) fwd_fft_kernel(const float* __restrict__ x) {
  extern __shared__ float sm[];
  float* sre = sm;
  float* sim = sm + 128 * 129;
  int img = blockIdx.x;
  int tid = threadIdx.x;
  int warp = tid >> 5, lane = tid & 31;
  float2 tw[7];
  make_twiddles<-1>(lane, tw);
  const float* xb = x + (size_t)img * 16384;

  // row pass (transform along columns for each row); fold ortho scale 1/128 and fftshift
  for (int r = warp; r < 128; r += 16) {
    float2 v[4];
#pragma unroll
    for (int s = 0; s < 4; s++)
      v[s] = make_float2(xb[r * 128 + s * 32 + lane] * 0.0078125f, 0.f);
    fft128(v, tw, lane);
#pragma unroll
    for (int s = 0; s < 4; s++) {
      int p = s * 32 + lane;
      int n = bitrev7(p) ^ 64;
      sre[r * 129 + n] = v[s].x;
      sim[r * 129 + n] = v[s].y;
    }
  }
  __syncthreads();
  // column pass, in-place per column (warp-private columns, reads precede writes)
  for (int c = warp; c < 128; c += 16) {
    float2 v[4];
#pragma unroll
    for (int s = 0; s < 4; s++) {
      int p = s * 32 + lane;
      v[s] = make_float2(sre[p * 129 + c], sim[p * 129 + c]);
    }
    fft128(v, tw, lane);
#pragma unroll
    for (int s = 0; s < 4; s++) {
      int p = s * 32 + lane;
      int n = bitrev7(p) ^ 64;
      sre[n * 129 + c] = v[s].x;
      sim[n * 129 + c] = v[s].y;
    }
  }
  __syncthreads();
  float2* Fb = g_F + (size_t)img * 16384;
  for (int i = tid; i < 16384; i += 512) {
    int r = i >> 7, c = i & 127;
    Fb[i] = make_float2(sre[r * 129 + c], sim[r * 129 + c]);
  }
}

// ---------------- tiny path: center magnitudes -> MLP -> anisotropic kernel ----------------
__global__ void __launch_bounds__(256) mlp_kernel(const float* __restrict__ w1, const float* __restrict__ b1,
                                                  const float* __restrict__ w2, const float* __restrict__ b2) {
  int b = blockIdx.x;
  int t = threadIdx.x;
  __shared__ float part[49][4];
  __shared__ float flat[49];
  __shared__ float hbuf[32];
  __shared__ float prm[3];
  __shared__ float kv[49];
  __shared__ float ksum;

  if (t < 196) {
    int p = t >> 2, q = t & 3;
    int i = p / 7, j = p % 7;
    const float2* Fp = g_F + ((size_t)b * 256) * 16384 + (61 + i) * 128 + (61 + j);
    float s = 0.f;
#pragma unroll 8
    for (int ch = q * 64; ch < q * 64 + 64; ch++) {
      float2 f = Fp[(size_t)ch * 16384];
      s += sqrtf(f.x * f.x + f.y * f.y);
    }
    part[p][q] = s;
  }
  __syncthreads();
  if (t < 49) flat[t] = (part[t][0] + part[t][1] + part[t][2] + part[t][3]) * (1.f / 256.f);
  __syncthreads();
  if (t < 32) {
    float a = b1[t];
#pragma unroll
    for (int i = 0; i < 49; i++) a += flat[i] * w1[t * 49 + i];
    hbuf[t] = fmaxf(a, 0.f);
  }
  __syncthreads();
  if (t < 3) {
    float a = b2[t];
#pragma unroll
    for (int u = 0; u < 32; u++) a += hbuf[u] * w2[t * 32 + u];
    prm[t] = a;
  }
  __syncthreads();
  if (t < 49) {
    float theta = atan2f(prm[0], prm[1]) * 0.5f + (float)M_PI * 0.5f;
    float lam1 = expf(prm[2]);
    float lam2 = 1.f / (lam1 + 1e-8f);
    float ct = cosf(theta), st = sinf(theta);
    int i = t / 7, j = t % 7;
    float yy = (float)(i - 3), xx = (float)(j - 3);
    float xr = xx * ct + yy * st;
    float yr = -xx * st + yy * ct;
    kv[t] = expf(-(xr * xr / (2.f * lam1 * lam1) + yr * yr / (2.f * lam2 * lam2)));
  }
  __syncthreads();
  if (t == 0) {
    float s = 0.f;
    for (int i = 0; i < 49; i++) s += kv[i];
    ksum = s;
  }
  __syncthreads();
  if (t < 49) g_kern[b * 49 + t] = kv[t] / (ksum + 1e-8f);
}

// ---------------- depthwise 7x7 correlation (zero pad) on shifted spectrum ----------------
__global__ void __launch_bounds__(256) conv_kernel() {
  __shared__ float2 tile[22][134];
  __shared__ float kc[49];
  int img = blockIdx.x;
  int b = img >> 8;
  int rBase = blockIdx.y * 16;
  int tid = threadIdx.x;
  if (tid < 49) kc[tid] = g_kern[b * 49 + tid];
  const float2* Fb = g_F + (size_t)img * 16384;
  for (int idx = tid; idx < 22 * 134; idx += 256) {
    int tr = idx / 134, tc = idx % 134;
    int gr = rBase - 3 + tr, gc = tc - 3;
    float2 val = make_float2(0.f, 0.f);
    if (gr >= 0 && gr < 128 && gc >= 0 && gc < 128) val = Fb[gr * 128 + gc];
    tile[tr][tc] = val;
  }
  __syncthreads();
  int w = tid & 127, rg = tid >> 7;
  float2* Gb = g_G + (size_t)img * 16384;
#pragma unroll
  for (int rr = 0; rr < 8; rr++) {
    int rl = rg * 8 + rr;
    float sre = 0.f, simv = 0.f;
#pragma unroll
    for (int dy = 0; dy < 7; dy++)
#pragma unroll
      for (int dx = 0; dx < 7; dx++) {
        float2 in = tile[rl + dy][w + dx];
        float k = kc[dy * 7 + dx];
        sre += in.x * k;
        simv += in.y * k;
      }
    Gb[(rBase + rl) * 128 + w] = make_float2(sre, simv);
  }
}

// ---------------- inverse FFT (with ifftshift) -> real part -> g_R ----------------
__global__ void __launch_bounds__(512) inv_fft_kernel() {
  extern __shared__ float sm[];
  float* sre = sm;
  float* sim = sm + 128 * 129;
  int img = blockIdx.x;
  int tid = threadIdx.x;
  int warp = tid >> 5, lane = tid & 31;
  float2 tw[7];
  make_twiddles<1>(lane, tw);
  const float2* Gb = g_G + (size_t)img * 16384;

  for (int r = warp; r < 128; r += 16) {
    float2 v[4];
#pragma unroll
    for (int s = 0; s < 4; s++) {
      int cidx = (s * 32 + lane) ^ 64;  // ifftshift on cols
      float2 g = Gb[r * 128 + cidx];
      v[s] = make_float2(g.x * 0.0078125f, g.y * 0.0078125f);  // ortho scale
    }
    fft128(v, tw, lane);
#pragma unroll
    for (int s = 0; s < 4; s++) {
      int p = s * 32 + lane;
      int n = bitrev7(p);
      sre[r * 129 + n] = v[s].x;
      sim[r * 129 + n] = v[s].y;
    }
  }
  __syncthreads();
  for (int c = warp; c < 128; c += 16) {
    float2 v[4];
#pragma unroll
    for (int s = 0; s < 4; s++) {
      int ridx = (s * 32 + lane) ^ 64;  // ifftshift on rows
      v[s] = make_float2(sre[ridx * 129 + c], sim[ridx * 129 + c]);
    }
    fft128(v, tw, lane);
#pragma unroll
    for (int s = 0; s < 4; s++) {
      int p = s * 32 + lane;
      sre[bitrev7(p) * 129 + c] = v[s].x;  // only real part needed
    }
  }
  __syncthreads();
  float* Rb = g_R + (size_t)img * 16384;
  for (int i = tid; i < 16384; i += 512) {
    int r = i >> 7, c = i & 127;
    Rb[i] = sre[r * 129 + c];
  }
}

// ---------------- transpose refine_w into Wt[c][o] ----------------
__global__ void transpose_w(const float* __restrict__ W) {
  __shared__ float tile[32][33];
  int tx = threadIdx.x, ty = threadIdx.y;
  int bx = blockIdx.x, by = blockIdx.y;
  tile[ty][tx] = W[(by * 32 + ty) * 256 + bx * 32 + tx];
  __syncthreads();
  g_Wt[(bx * 32 + ty) * 256 + by * 32 + tx] = tile[tx][ty];
}

// ---------------- channel mix GEMM + bilinear-upsample epilogue ----------------
// out[b][o][h][w] = sum_c W[o][c]*g_R[b][c][h][w] + bilinear_up(x_high)[b][o][h][w]
__global__ void __launch_bounds__(256) mix_kernel(const float* __restrict__ xh, float* __restrict__ out) {
  int b = blockIdx.z;
  int h = blockIdx.x;
  int oBase = blockIdx.y * 128;
  int tid = threadIdx.x;
  __shared__ float As[8][128];
  __shared__ float Bs[8][128];
  const float* Rb = g_R + (size_t)b * 256 * 16384 + h * 128;

  float acc[8][8];
#pragma unroll
  for (int i = 0; i < 8; i++)
#pragma unroll
    for (int j = 0; j < 8; j++) acc[i][j] = 0.f;

  int ty = tid >> 4, tx = tid & 15;
  int lk = tid >> 5;           // 0..7
  int lo = (tid & 31) * 4;     // 0..124

  for (int kb = 0; kb < 256; kb += 8) {
    __syncthreads();
    *(float4*)&As[lk][lo] = *(const float4*)&g_Wt[(kb + lk) * 256 + oBase + lo];
    *(float4*)&Bs[lk][lo] = *(const float4*)&Rb[(size_t)(kb + lk) * 16384 + lo];
    __syncthreads();
#pragma unroll
    for (int kk = 0; kk < 8; kk++) {
      float ra[8], rb[8];
      *(float4*)(ra) = *(const float4*)&As[kk][ty * 8];
      *(float4*)(ra + 4) = *(const float4*)&As[kk][ty * 8 + 4];
      *(float4*)(rb) = *(const float4*)&Bs[kk][tx * 8];
      *(float4*)(rb + 4) = *(const float4*)&Bs[kk][tx * 8 + 4];
#pragma unroll
      for (int i = 0; i < 8; i++)
#pragma unroll
        for (int j = 0; j < 8; j++) acc[i][j] += ra[i] * rb[j];
    }
  }

  // jax.image.resize bilinear (half-pixel, edge-renormalized == clamp at ends)
  float hin = 0.5f * (float)h - 0.25f;
  int hi0 = hin < 0.f ? 0 : (int)hin;
  float hf = hin < 0.f ? 0.f : hin - (float)hi0;
  int hi1 = hi0 + 1 < 64 ? hi0 + 1 : 63;

  int wi0[8], wi1[8];
  float wf[8];
#pragma unroll
  for (int j = 0; j < 8; j++) {
    int w = tx * 8 + j;
    float win = 0.5f * (float)w - 0.25f;
    wi0[j] = win < 0.f ? 0 : (int)win;
    wf[j] = win < 0.f ? 0.f : win - (float)wi0[j];
    wi1[j] = wi0[j] + 1 < 64 ? wi0[j] + 1 : 63;
  }
#pragma unroll
  for (int i = 0; i < 8; i++) {
    int o = oBase + ty * 8 + i;
    const float* xb = xh + (size_t)(b * 256 + o) * 4096;
    const float* r0 = xb + hi0 * 64;
    const float* r1 = xb + hi1 * 64;
    float vals[8];
#pragma unroll
    for (int j = 0; j < 8; j++) {
      float top = r0[wi0[j]] * (1.f - wf[j]) + r0[wi1[j]] * wf[j];
      float bot = r1[wi0[j]] * (1.f - wf[j]) + r1[wi1[j]] * wf[j];
      vals[j] = acc[i][j] + top * (1.f - hf) + bot * hf;
    }
    float* op = out + (size_t)(b * 256 + o) * 16384 + h * 128 + tx * 8;
    *(float4*)op = *(float4*)vals;
    *(float4*)(op + 4) = *(float4*)(vals + 4);
  }
}

// ---------------- launch ----------------
extern "C" void kernel_launch(void* const* d_in, const int* in_sizes, int n_in,
                              void* d_out, int out_size) {
  const float* x_high = (const float*)d_in[0];
  const float* x_low = (const float*)d_in[1];
  const float* w1 = (const float*)d_in[2];
  const float* b1 = (const float*)d_in[3];
  const float* w2 = (const float*)d_in[4];
  const float* b2 = (const float*)d_in[5];
  const float* refine_w = (const float*)d_in[6];
  float* out = (float*)d_out;

  const int SMEM_FFT = 2 * 128 * 129 * 4;  // 132096 B
  cudaFuncSetAttribute((const void*)fwd_fft_kernel, cudaFuncAttributeMaxDynamicSharedMemorySize, SMEM_FFT);
  cudaFuncSetAttribute((const void*)inv_fft_kernel, cudaFuncAttributeMaxDynamicSharedMemorySize, SMEM_FFT);

  transpose_w<<<dim3(8, 8), dim3(32, 32)>>>(refine_w);
  fwd_fft_kernel<<<2048, 512, SMEM_FFT>>>(x_low);
  mlp_kernel<<<8, 256>>>(w1, b1, w2, b2);
  conv_kernel<<<dim3(2048, 8), 256>>>();
  inv_fft_kernel<<<2048, 512, SMEM_FFT>>>();
  mix_kernel<<<dim3(128, 2, 8), 256>>>(x_high, out);
}

// round 5
// speedup vs baseline: 1.1279x; 1.1279x over previous
#include <cuda_runtime.h>
#include <math.h>

#ifndef M_PI
#define M_PI 3.14159265358979323846
#endif

#define FULLMASK 0xffffffffu

// ---------------- scratch (static device globals; no allocations) ----------------
__device__ float2 g_F[33554432];   // shifted FFT of x_low   (B*C,128,128) complex
__device__ float2 g_G[33554432];   // conv output            (B*C,128,128) complex
__device__ float  g_R[33554432];   // real(ifft2)            (B*C,128,128) float
__device__ float  g_kern[8 * 49];  // per-batch 7x7 kernel
__device__ float  g_Wt[256 * 256]; // refine_w transposed: Wt[c][o] = W[o][c]

// ---------------- complex helpers ----------------
__device__ __forceinline__ float2 cadd(float2 a, float2 b) { return make_float2(a.x + b.x, a.y + b.y); }
__device__ __forceinline__ float2 csub(float2 a, float2 b) { return make_float2(a.x - b.x, a.y - b.y); }
__device__ __forceinline__ float2 cmul(float2 a, float2 b) {
  return make_float2(a.x * b.x - a.y * b.y, a.x * b.y + a.y * b.x);
}

// ---------------- warp-resident 128-pt DIF FFT ----------------
// Lane l holds positions p = s*32 + l, s = 0..3.  Natural input -> bit-reversed output.
template<int SGN>
__device__ __forceinline__ void make_twiddles(int lane, float2 tw[7]) {
  const float TP = 6.283185307179586f * (float)SGN;
  float fr[7] = { lane / 128.f, (lane + 32) / 128.f, lane / 64.f,
                  (lane & 15) / 32.f, (lane & 7) / 16.f, (lane & 3) / 8.f, (lane & 1) / 4.f };
#pragma unroll
  for (int i = 0; i < 7; i++) {
    float s, c;
    sincosf(TP * fr[i], &s, &c);
    tw[i] = make_float2(c, s);
  }
}

__device__ __forceinline__ void fft128(float2 v[4], const float2 tw[7], int lane) {
  float2 t, u;
  t = v[0]; u = v[2]; v[0] = cadd(t, u); v[2] = cmul(csub(t, u), tw[0]);
  t = v[1]; u = v[3]; v[1] = cadd(t, u); v[3] = cmul(csub(t, u), tw[1]);
  t = v[0]; u = v[1]; v[0] = cadd(t, u); v[1] = cmul(csub(t, u), tw[2]);
  t = v[2]; u = v[3]; v[2] = cadd(t, u); v[3] = cmul(csub(t, u), tw[2]);
#pragma unroll
  for (int hi = 0; hi < 5; hi++) {
    int h = 16 >> hi;
    bool up = (lane & h) != 0;
#pragma unroll
    for (int s = 0; s < 4; s++) {
      float prx = __shfl_xor_sync(FULLMASK, v[s].x, h);
      float pry = __shfl_xor_sync(FULLMASK, v[s].y, h);
      float2 pr = make_float2(prx, pry);
      if (hi < 4) {
        v[s] = up ? cmul(csub(pr, v[s]), tw[3 + hi]) : cadd(v[s], pr);
      } else {
        v[s] = up ? csub(pr, v[s]) : cadd(v[s], pr);
      }
    }
  }
}

__device__ __forceinline__ int bitrev7(int p) { return (int)(__brev((unsigned)p) >> 25); }

// ---------------- forward FFT (channel-pair packed): x_low -> g_F ----------------
// One block per channel PAIR (2c, 2c+1).  z = x1 + i*x2 ; FFT2(z) shifted in smem;
// Hermitian unpack: F1 = (Z(n)+conj(Z(m)))/2 , F2 = (Z(n)-conj(Z(m)))/(2i), m = mirror.
__global__ void __launch_bounds__(1024) fwd_fft_pair_kernel(const float* __restrict__ x) {
  extern __shared__ float sm[];
  float* sre = sm;
  float* sim = sm + 128 * 129;
  int pair = blockIdx.x;          // 0..1023
  int ch1 = pair * 2, ch2 = ch1 + 1;
  int tid = threadIdx.x;
  int warp = tid >> 5, lane = tid & 31;
  float2 tw[7];
  make_twiddles<-1>(lane, tw);
  const float* x1 = x + (size_t)ch1 * 16384;
  const float* x2 = x + (size_t)ch2 * 16384;

  // row pass; fold ortho scale 1/128 (once for the 2D pair) and fftshift on cols
  for (int r = warp; r < 128; r += 32) {
    float2 v[4];
#pragma unroll
    for (int s = 0; s < 4; s++) {
      int c = s * 32 + lane;
      v[s] = make_float2(x1[r * 128 + c] * 0.0078125f, x2[r * 128 + c] * 0.0078125f);
    }
    fft128(v, tw, lane);
#pragma unroll
    for (int s = 0; s < 4; s++) {
      int p = s * 32 + lane;
      int n = bitrev7(p) ^ 64;
      sre[r * 129 + n] = v[s].x;
      sim[r * 129 + n] = v[s].y;
    }
  }
  __syncthreads();
  // column pass (warp-private columns, in-place)
  for (int c = warp; c < 128; c += 32) {
    float2 v[4];
#pragma unroll
    for (int s = 0; s < 4; s++) {
      int p = s * 32 + lane;
      v[s] = make_float2(sre[p * 129 + c], sim[p * 129 + c]);
    }
    fft128(v, tw, lane);
#pragma unroll
    for (int s = 0; s < 4; s++) {
      int p = s * 32 + lane;
      int n = bitrev7(p) ^ 64;
      sre[n * 129 + c] = v[s].x;
      sim[n * 129 + c] = v[s].y;
    }
  }
  __syncthreads();
  // Hermitian unpack + store both channels
  float2* F1 = g_F + (size_t)ch1 * 16384;
  float2* F2 = g_F + (size_t)ch2 * 16384;
  for (int i = tid; i < 16384; i += 1024) {
    int r = i >> 7, c = i & 127;
    int mr = (128 - r) & 127, mc = (128 - c) & 127;
    float a = sre[r * 129 + c],  b = sim[r * 129 + c];
    float cc = sre[mr * 129 + mc], d = sim[mr * 129 + mc];
    F1[i] = make_float2((a + cc) * 0.5f, (b - d) * 0.5f);
    F2[i] = make_float2((b + d) * 0.5f, (cc - a) * 0.5f);
  }
}

// ---------------- tiny path: center magnitudes -> MLP -> anisotropic kernel ----------------
__global__ void __launch_bounds__(256) mlp_kernel(const float* __restrict__ w1, const float* __restrict__ b1,
                                                  const float* __restrict__ w2, const float* __restrict__ b2) {
  int b = blockIdx.x;
  int t = threadIdx.x;
  __shared__ float part[49][4];
  __shared__ float flat[49];
  __shared__ float hbuf[32];
  __shared__ float prm[3];
  __shared__ float kv[49];
  __shared__ float ksum;

  if (t < 196) {
    int p = t >> 2, q = t & 3;
    int i = p / 7, j = p % 7;
    const float2* Fp = g_F + ((size_t)b * 256) * 16384 + (61 + i) * 128 + (61 + j);
    float s = 0.f;
#pragma unroll 8
    for (int ch = q * 64; ch < q * 64 + 64; ch++) {
      float2 f = Fp[(size_t)ch * 16384];
      s += sqrtf(f.x * f.x + f.y * f.y);
    }
    part[p][q] = s;
  }
  __syncthreads();
  if (t < 49) flat[t] = (part[t][0] + part[t][1] + part[t][2] + part[t][3]) * (1.f / 256.f);
  __syncthreads();
  if (t < 32) {
    float a = b1[t];
#pragma unroll
    for (int i = 0; i < 49; i++) a += flat[i] * w1[t * 49 + i];
    hbuf[t] = fmaxf(a, 0.f);
  }
  __syncthreads();
  if (t < 3) {
    float a = b2[t];
#pragma unroll
    for (int u = 0; u < 32; u++) a += hbuf[u] * w2[t * 32 + u];
    prm[t] = a;
  }
  __syncthreads();
  if (t < 49) {
    float theta = atan2f(prm[0], prm[1]) * 0.5f + (float)M_PI * 0.5f;
    float lam1 = expf(prm[2]);
    float lam2 = 1.f / (lam1 + 1e-8f);
    float ct = cosf(theta), st = sinf(theta);
    int i = t / 7, j = t % 7;
    float yy = (float)(i - 3), xx = (float)(j - 3);
    float xr = xx * ct + yy * st;
    float yr = -xx * st + yy * ct;
    kv[t] = expf(-(xr * xr / (2.f * lam1 * lam1) + yr * yr / (2.f * lam2 * lam2)));
  }
  __syncthreads();
  if (t == 0) {
    float s = 0.f;
    for (int i = 0; i < 49; i++) s += kv[i];
    ksum = s;
  }
  __syncthreads();
  if (t < 49) g_kern[b * 49 + t] = kv[t] / (ksum + 1e-8f);
}

// ---------------- depthwise 7x7 correlation (zero pad), register-rolling rows ----------------
__global__ void __launch_bounds__(256) conv_kernel() {
  __shared__ float2 tile[22][134];
  __shared__ float kc[49];
  int img = blockIdx.x;
  int b = img >> 8;
  int rBase = blockIdx.y * 16;
  int tid = threadIdx.x;
  if (tid < 49) kc[tid] = g_kern[b * 49 + tid];
  const float2* Fb = g_F + (size_t)img * 16384;
  for (int idx = tid; idx < 22 * 134; idx += 256) {
    int tr = idx / 134, tc = idx % 134;
    int gr = rBase - 3 + tr, gc = tc - 3;
    float2 val = make_float2(0.f, 0.f);
    if (gr >= 0 && gr < 128 && gc >= 0 && gc < 128) val = Fb[gr * 128 + gc];
    tile[tr][tc] = val;
  }
  __syncthreads();
  int w = tid & 127, rg = tid >> 7;
  int base = rg * 8;
  float accx[8], accy[8];
#pragma unroll
  for (int o = 0; o < 8; o++) { accx[o] = 0.f; accy[o] = 0.f; }
  // sweep 14 input rows; each contributes to outputs o = t-6 .. t
#pragma unroll
  for (int t = 0; t < 14; t++) {
    float2 a[7];
#pragma unroll
    for (int dx = 0; dx < 7; dx++) a[dx] = tile[base + t][w + dx];
#pragma unroll
    for (int o = 0; o < 8; o++) {
      int dy = t - o;
      if (dy >= 0 && dy < 7) {
#pragma unroll
        for (int dx = 0; dx < 7; dx++) {
          float k = kc[dy * 7 + dx];
          accx[o] += a[dx].x * k;
          accy[o] += a[dx].y * k;
        }
      }
    }
  }
  float2* Gb = g_G + (size_t)img * 16384;
#pragma unroll
  for (int o = 0; o < 8; o++) {
    Gb[(rBase + base + o) * 128 + w] = make_float2(accx[o], accy[o]);
  }
}

// ---------------- inverse FFT (Hermitian channel-pair): g_G -> g_R ----------------
// real(ifft(G)) = ifft(Herm(G)).  W = Herm(G1) + i*Herm(G2): one complex IFFT gives
// real part -> channel 2c, imag part -> channel 2c+1.  ifftshift folded into indexing.
__global__ void __launch_bounds__(1024) inv_fft_pair_kernel() {
  extern __shared__ float sm[];
  float* sre = sm;
  float* sim = sm + 128 * 129;
  int pair = blockIdx.x;
  int ch1 = pair * 2, ch2 = ch1 + 1;
  int tid = threadIdx.x;
  int warp = tid >> 5, lane = tid & 31;
  float2 tw[7];
  make_twiddles<1>(lane, tw);
  const float2* G1 = g_G + (size_t)ch1 * 16384;
  const float2* G2 = g_G + (size_t)ch2 * 16384;

  // row pass: build W on the fly (Herm-combine at n and mirror m), ifftshift on cols
  for (int r = warp; r < 128; r += 32) {
    int mr = (128 - r) & 127;
    float2 v[4];
#pragma unroll
    for (int s = 0; s < 4; s++) {
      int cidx = (s * 32 + lane) ^ 64;      // ifftshift on cols
      int mc = (128 - cidx) & 127;
      float2 A1 = G1[r * 128 + cidx];
      float2 B1 = G1[mr * 128 + mc];
      float2 A2 = G2[r * 128 + cidx];
      float2 B2 = G2[mr * 128 + mc];
      // W = ((A1+conj(B1)) + i(A2+conj(B2)))/2 , fold ortho 1/128 -> *0.00390625
      v[s] = make_float2((A1.x + B1.x - A2.y + B2.y) * 0.00390625f,
                         (A1.y - B1.y + A2.x + B2.x) * 0.00390625f);
    }
    fft128(v, tw, lane);
#pragma unroll
    for (int s = 0; s < 4; s++) {
      int p = s * 32 + lane;
      int n = bitrev7(p);
      sre[r * 129 + n] = v[s].x;
      sim[r * 129 + n] = v[s].y;
    }
  }
  __syncthreads();
  // column pass with ifftshift on rows; keep BOTH re (ch1) and im (ch2)
  for (int c = warp; c < 128; c += 32) {
    float2 v[4];
#pragma unroll
    for (int s = 0; s < 4; s++) {
      int ridx = (s * 32 + lane) ^ 64;
      v[s] = make_float2(sre[ridx * 129 + c], sim[ridx * 129 + c]);
    }
    fft128(v, tw, lane);
#pragma unroll
    for (int s = 0; s < 4; s++) {
      int p = s * 32 + lane;
      int n = bitrev7(p);
      sre[n * 129 + c] = v[s].x;
      sim[n * 129 + c] = v[s].y;
    }
  }
  __syncthreads();
  float* R1 = g_R + (size_t)ch1 * 16384;
  float* R2 = g_R + (size_t)ch2 * 16384;
  for (int i = tid; i < 16384; i += 1024) {
    int r = i >> 7, c = i & 127;
    R1[i] = sre[r * 129 + c];
    R2[i] = sim[r * 129 + c];
  }
}

// ---------------- transpose refine_w into Wt[c][o] ----------------
__global__ void transpose_w(const float* __restrict__ W) {
  __shared__ float tile[32][33];
  int tx = threadIdx.x, ty = threadIdx.y;
  int bx = blockIdx.x, by = blockIdx.y;
  tile[ty][tx] = W[(by * 32 + ty) * 256 + bx * 32 + tx];
  __syncthreads();
  g_Wt[(bx * 32 + ty) * 256 + by * 32 + tx] = tile[tx][ty];
}

// ---------------- channel mix GEMM + bilinear-upsample epilogue ----------------
__global__ void __launch_bounds__(256) mix_kernel(const float* __restrict__ xh, float* __restrict__ out) {
  int b = blockIdx.z;
  int h = blockIdx.x;
  int oBase = blockIdx.y * 128;
  int tid = threadIdx.x;
  __shared__ float As[8][128];
  __shared__ float Bs[8][128];
  const float* Rb = g_R + (size_t)b * 256 * 16384 + h * 128;

  float acc[8][8];
#pragma unroll
  for (int i = 0; i < 8; i++)
#pragma unroll
    for (int j = 0; j < 8; j++) acc[i][j] = 0.f;

  int ty = tid >> 4, tx = tid & 15;
  int lk = tid >> 5;
  int lo = (tid & 31) * 4;

  for (int kb = 0; kb < 256; kb += 8) {
    __syncthreads();
    *(float4*)&As[lk][lo] = *(const float4*)&g_Wt[(kb + lk) * 256 + oBase + lo];
    *(float4*)&Bs[lk][lo] = *(const float4*)&Rb[(size_t)(kb + lk) * 16384 + lo];
    __syncthreads();
#pragma unroll
    for (int kk = 0; kk < 8; kk++) {
      float ra[8], rb[8];
      *(float4*)(ra) = *(const float4*)&As[kk][ty * 8];
      *(float4*)(ra + 4) = *(const float4*)&As[kk][ty * 8 + 4];
      *(float4*)(rb) = *(const float4*)&Bs[kk][tx * 8];
      *(float4*)(rb + 4) = *(const float4*)&Bs[kk][tx * 8 + 4];
#pragma unroll
      for (int i = 0; i < 8; i++)
#pragma unroll
        for (int j = 0; j < 8; j++) acc[i][j] += ra[i] * rb[j];
    }
  }

  float hin = 0.5f * (float)h - 0.25f;
  int hi0 = hin < 0.f ? 0 : (int)hin;
  float hf = hin < 0.f ? 0.f : hin - (float)hi0;
  int hi1 = hi0 + 1 < 64 ? hi0 + 1 : 63;

  int wi0[8], wi1[8];
  float wf[8];
#pragma unroll
  for (int j = 0; j < 8; j++) {
    int w = tx * 8 + j;
    float win = 0.5f * (float)w - 0.25f;
    wi0[j] = win < 0.f ? 0 : (int)win;
    wf[j] = win < 0.f ? 0.f : win - (float)wi0[j];
    wi1[j] = wi0[j] + 1 < 64 ? wi0[j] + 1 : 63;
  }
#pragma unroll
  for (int i = 0; i < 8; i++) {
    int o = oBase + ty * 8 + i;
    const float* xb = xh + (size_t)(b * 256 + o) * 4096;
    const float* r0 = xb + hi0 * 64;
    const float* r1 = xb + hi1 * 64;
    float vals[8];
#pragma unroll
    for (int j = 0; j < 8; j++) {
      float top = r0[wi0[j]] * (1.f - wf[j]) + r0[wi1[j]] * wf[j];
      float bot = r1[wi0[j]] * (1.f - wf[j]) + r1[wi1[j]] * wf[j];
      vals[j] = acc[i][j] + top * (1.f - hf) + bot * hf;
    }
    float* op = out + (size_t)(b * 256 + o) * 16384 + h * 128 + tx * 8;
    *(float4*)op = *(float4*)vals;
    *(float4*)(op + 4) = *(float4*)(vals + 4);
  }
}

// ---------------- launch ----------------
extern "C" void kernel_launch(void* const* d_in, const int* in_sizes, int n_in,
                              void* d_out, int out_size) {
  const float* x_high = (const float*)d_in[0];
  const float* x_low = (const float*)d_in[1];
  const float* w1 = (const float*)d_in[2];
  const float* b1 = (const float*)d_in[3];
  const float* w2 = (const float*)d_in[4];
  const float* b2 = (const float*)d_in[5];
  const float* refine_w = (const float*)d_in[6];
  float* out = (float*)d_out;

  const int SMEM_FFT = 2 * 128 * 129 * 4;  // 132096 B
  cudaFuncSetAttribute((const void*)fwd_fft_pair_kernel, cudaFuncAttributeMaxDynamicSharedMemorySize, SMEM_FFT);
  cudaFuncSetAttribute((const void*)inv_fft_pair_kernel, cudaFuncAttributeMaxDynamicSharedMemorySize, SMEM_FFT);

  transpose_w<<<dim3(8, 8), dim3(32, 32)>>>(refine_w);
  fwd_fft_pair_kernel<<<1024, 1024, SMEM_FFT>>>(x_low);
  mlp_kernel<<<8, 256>>>(w1, b1, w2, b2);
  conv_kernel<<<dim3(2048, 8), 256>>>();
  inv_fft_pair_kernel<<<1024, 1024, SMEM_FFT>>>();
  mix_kernel<<<dim3(128, 2, 8), 256>>>(x_high, out);
}

// round 6
// speedup vs baseline: 1.2923x; 1.1457x over previous
#include <cuda_runtime.h>
#include <math.h>
#include <stdint.h>

#ifndef M_PI
#define M_PI 3.14159265358979323846
#endif

#define FULLMASK 0xffffffffu

// ---------------- scratch (static device globals; no allocations) ----------------
__device__ float2 g_F[33554432];   // shifted FFT of x_low   (B*C,128,128) complex
__device__ float2 g_G[33554432];   // conv output            (B*C,128,128) complex
__device__ float  g_R[33554432];   // real(ifft2)            (B*C,128,128) float
__device__ float  g_kern[8 * 49];  // per-batch 7x7 kernel
__device__ float  g_Wt[256 * 256]; // refine_w transposed: Wt[c][o] = W[o][c]

// ---------------- complex helpers ----------------
__device__ __forceinline__ float2 cadd(float2 a, float2 b) { return make_float2(a.x + b.x, a.y + b.y); }
__device__ __forceinline__ float2 csub(float2 a, float2 b) { return make_float2(a.x - b.x, a.y - b.y); }
__device__ __forceinline__ float2 cmul(float2 a, float2 b) {
  return make_float2(a.x * b.x - a.y * b.y, a.x * b.y + a.y * b.x);
}

// ---------------- warp-resident 128-pt DIF FFT ----------------
template<int SGN>
__device__ __forceinline__ void make_twiddles(int lane, float2 tw[7]) {
  const float TP = 6.283185307179586f * (float)SGN;
  float fr[7] = { lane / 128.f, (lane + 32) / 128.f, lane / 64.f,
                  (lane & 15) / 32.f, (lane & 7) / 16.f, (lane & 3) / 8.f, (lane & 1) / 4.f };
#pragma unroll
  for (int i = 0; i < 7; i++) {
    float s, c;
    sincosf(TP * fr[i], &s, &c);
    tw[i] = make_float2(c, s);
  }
}

__device__ __forceinline__ void fft128(float2 v[4], const float2 tw[7], int lane) {
  float2 t, u;
  t = v[0]; u = v[2]; v[0] = cadd(t, u); v[2] = cmul(csub(t, u), tw[0]);
  t = v[1]; u = v[3]; v[1] = cadd(t, u); v[3] = cmul(csub(t, u), tw[1]);
  t = v[0]; u = v[1]; v[0] = cadd(t, u); v[1] = cmul(csub(t, u), tw[2]);
  t = v[2]; u = v[3]; v[2] = cadd(t, u); v[3] = cmul(csub(t, u), tw[2]);
#pragma unroll
  for (int hi = 0; hi < 5; hi++) {
    int h = 16 >> hi;
    bool up = (lane & h) != 0;
#pragma unroll
    for (int s = 0; s < 4; s++) {
      float prx = __shfl_xor_sync(FULLMASK, v[s].x, h);
      float pry = __shfl_xor_sync(FULLMASK, v[s].y, h);
      float2 pr = make_float2(prx, pry);
      if (hi < 4) {
        v[s] = up ? cmul(csub(pr, v[s]), tw[3 + hi]) : cadd(v[s], pr);
      } else {
        v[s] = up ? csub(pr, v[s]) : cadd(v[s], pr);
      }
    }
  }
}

__device__ __forceinline__ int bitrev7(int p) { return (int)(__brev((unsigned)p) >> 25); }

// ---------------- forward FFT (channel-pair packed): x_low -> g_F ----------------
__global__ void __launch_bounds__(1024) fwd_fft_pair_kernel(const float* __restrict__ x) {
  extern __shared__ float sm[];
  float* sre = sm;
  float* sim = sm + 128 * 129;
  int pair = blockIdx.x;
  int ch1 = pair * 2, ch2 = ch1 + 1;
  int tid = threadIdx.x;
  int warp = tid >> 5, lane = tid & 31;
  float2 tw[7];
  make_twiddles<-1>(lane, tw);
  const float* x1 = x + (size_t)ch1 * 16384;
  const float* x2 = x + (size_t)ch2 * 16384;

  for (int r = warp; r < 128; r += 32) {
    float2 v[4];
#pragma unroll
    for (int s = 0; s < 4; s++) {
      int c = s * 32 + lane;
      v[s] = make_float2(x1[r * 128 + c] * 0.0078125f, x2[r * 128 + c] * 0.0078125f);
    }
    fft128(v, tw, lane);
#pragma unroll
    for (int s = 0; s < 4; s++) {
      int p = s * 32 + lane;
      int n = bitrev7(p) ^ 64;
      sre[r * 129 + n] = v[s].x;
      sim[r * 129 + n] = v[s].y;
    }
  }
  __syncthreads();
  for (int c = warp; c < 128; c += 32) {
    float2 v[4];
#pragma unroll
    for (int s = 0; s < 4; s++) {
      int p = s * 32 + lane;
      v[s] = make_float2(sre[p * 129 + c], sim[p * 129 + c]);
    }
    fft128(v, tw, lane);
#pragma unroll
    for (int s = 0; s < 4; s++) {
      int p = s * 32 + lane;
      int n = bitrev7(p) ^ 64;
      sre[n * 129 + c] = v[s].x;
      sim[n * 129 + c] = v[s].y;
    }
  }
  __syncthreads();
  float2* F1 = g_F + (size_t)ch1 * 16384;
  float2* F2 = g_F + (size_t)ch2 * 16384;
  for (int i = tid; i < 16384; i += 1024) {
    int r = i >> 7, c = i & 127;
    int mr = (128 - r) & 127, mc = (128 - c) & 127;
    float a = sre[r * 129 + c],  b = sim[r * 129 + c];
    float cc = sre[mr * 129 + mc], d = sim[mr * 129 + mc];
    F1[i] = make_float2((a + cc) * 0.5f, (b - d) * 0.5f);
    F2[i] = make_float2((b + d) * 0.5f, (cc - a) * 0.5f);
  }
}

// ---------------- tiny path: center magnitudes -> MLP -> anisotropic kernel ----------------
__global__ void __launch_bounds__(256) mlp_kernel(const float* __restrict__ w1, const float* __restrict__ b1,
                                                  const float* __restrict__ w2, const float* __restrict__ b2) {
  int b = blockIdx.x;
  int t = threadIdx.x;
  __shared__ float part[49][4];
  __shared__ float flat[49];
  __shared__ float hbuf[32];
  __shared__ float prm[3];
  __shared__ float kv[49];
  __shared__ float ksum;

  if (t < 196) {
    int p = t >> 2, q = t & 3;
    int i = p / 7, j = p % 7;
    const float2* Fp = g_F + ((size_t)b * 256) * 16384 + (61 + i) * 128 + (61 + j);
    float s = 0.f;
#pragma unroll 8
    for (int ch = q * 64; ch < q * 64 + 64; ch++) {
      float2 f = Fp[(size_t)ch * 16384];
      s += sqrtf(f.x * f.x + f.y * f.y);
    }
    part[p][q] = s;
  }
  __syncthreads();
  if (t < 49) flat[t] = (part[t][0] + part[t][1] + part[t][2] + part[t][3]) * (1.f / 256.f);
  __syncthreads();
  if (t < 32) {
    float a = b1[t];
#pragma unroll
    for (int i = 0; i < 49; i++) a += flat[i] * w1[t * 49 + i];
    hbuf[t] = fmaxf(a, 0.f);
  }
  __syncthreads();
  if (t < 3) {
    float a = b2[t];
#pragma unroll
    for (int u = 0; u < 32; u++) a += hbuf[u] * w2[t * 32 + u];
    prm[t] = a;
  }
  __syncthreads();
  if (t < 49) {
    float theta = atan2f(prm[0], prm[1]) * 0.5f + (float)M_PI * 0.5f;
    float lam1 = expf(prm[2]);
    float lam2 = 1.f / (lam1 + 1e-8f);
    float ct = cosf(theta), st = sinf(theta);
    int i = t / 7, j = t % 7;
    float yy = (float)(i - 3), xx = (float)(j - 3);
    float xr = xx * ct + yy * st;
    float yr = -xx * st + yy * ct;
    kv[t] = expf(-(xr * xr / (2.f * lam1 * lam1) + yr * yr / (2.f * lam2 * lam2)));
  }
  __syncthreads();
  if (t == 0) {
    float s = 0.f;
    for (int i = 0; i < 49; i++) s += kv[i];
    ksum = s;
  }
  __syncthreads();
  if (t < 49) g_kern[b * 49 + t] = kv[t] / (ksum + 1e-8f);
}

// ---------------- depthwise 7x7 correlation (zero pad) — R3 version (best measured) ----------------
__global__ void __launch_bounds__(256) conv_kernel() {
  __shared__ float2 tile[22][134];
  __shared__ float kc[49];
  int img = blockIdx.x;
  int b = img >> 8;
  int rBase = blockIdx.y * 16;
  int tid = threadIdx.x;
  if (tid < 49) kc[tid] = g_kern[b * 49 + tid];
  const float2* Fb = g_F + (size_t)img * 16384;
  for (int idx = tid; idx < 22 * 134; idx += 256) {
    int tr = idx / 134, tc = idx % 134;
    int gr = rBase - 3 + tr, gc = tc - 3;
    float2 val = make_float2(0.f, 0.f);
    if (gr >= 0 && gr < 128 && gc >= 0 && gc < 128) val = Fb[gr * 128 + gc];
    tile[tr][tc] = val;
  }
  __syncthreads();
  int w = tid & 127, rg = tid >> 7;
  float2* Gb = g_G + (size_t)img * 16384;
#pragma unroll
  for (int rr = 0; rr < 8; rr++) {
    int rl = rg * 8 + rr;
    float sre = 0.f, simv = 0.f;
#pragma unroll
    for (int dy = 0; dy < 7; dy++)
#pragma unroll
      for (int dx = 0; dx < 7; dx++) {
        float2 in = tile[rl + dy][w + dx];
        float k = kc[dy * 7 + dx];
        sre += in.x * k;
        simv += in.y * k;
      }
    Gb[(rBase + rl) * 128 + w] = make_float2(sre, simv);
  }
}

// ---------------- inverse FFT (Hermitian channel-pair): g_G -> g_R ----------------
__global__ void __launch_bounds__(1024) inv_fft_pair_kernel() {
  extern __shared__ float sm[];
  float* sre = sm;
  float* sim = sm + 128 * 129;
  int pair = blockIdx.x;
  int ch1 = pair * 2, ch2 = ch1 + 1;
  int tid = threadIdx.x;
  int warp = tid >> 5, lane = tid & 31;
  float2 tw[7];
  make_twiddles<1>(lane, tw);
  const float2* G1 = g_G + (size_t)ch1 * 16384;
  const float2* G2 = g_G + (size_t)ch2 * 16384;

  for (int r = warp; r < 128; r += 32) {
    int mr = (128 - r) & 127;
    float2 v[4];
#pragma unroll
    for (int s = 0; s < 4; s++) {
      int cidx = (s * 32 + lane) ^ 64;
      int mc = (128 - cidx) & 127;
      float2 A1 = G1[r * 128 + cidx];
      float2 B1 = G1[mr * 128 + mc];
      float2 A2 = G2[r * 128 + cidx];
      float2 B2 = G2[mr * 128 + mc];
      v[s] = make_float2((A1.x + B1.x - A2.y + B2.y) * 0.00390625f,
                         (A1.y - B1.y + A2.x + B2.x) * 0.00390625f);
    }
    fft128(v, tw, lane);
#pragma unroll
    for (int s = 0; s < 4; s++) {
      int p = s * 32 + lane;
      int n = bitrev7(p);
      sre[r * 129 + n] = v[s].x;
      sim[r * 129 + n] = v[s].y;
    }
  }
  __syncthreads();
  for (int c = warp; c < 128; c += 32) {
    float2 v[4];
#pragma unroll
    for (int s = 0; s < 4; s++) {
      int ridx = (s * 32 + lane) ^ 64;
      v[s] = make_float2(sre[ridx * 129 + c], sim[ridx * 129 + c]);
    }
    fft128(v, tw, lane);
#pragma unroll
    for (int s = 0; s < 4; s++) {
      int p = s * 32 + lane;
      int n = bitrev7(p);
      sre[n * 129 + c] = v[s].x;
      sim[n * 129 + c] = v[s].y;
    }
  }
  __syncthreads();
  float* R1 = g_R + (size_t)ch1 * 16384;
  float* R2 = g_R + (size_t)ch2 * 16384;
  for (int i = tid; i < 16384; i += 1024) {
    int r = i >> 7, c = i & 127;
    R1[i] = sre[r * 129 + c];
    R2[i] = sim[r * 129 + c];
  }
}

// ---------------- transpose refine_w into Wt[c][o] ----------------
__global__ void transpose_w(const float* __restrict__ W) {
  __shared__ float tile[32][33];
  int tx = threadIdx.x, ty = threadIdx.y;
  int bx = blockIdx.x, by = blockIdx.y;
  tile[ty][tx] = W[(by * 32 + ty) * 256 + bx * 32 + tx];
  __syncthreads();
  g_Wt[(bx * 32 + ty) * 256 + by * 32 + tx] = tile[tx][ty];
}

// ---------------- TF32 tensor-core helpers ----------------
__device__ __forceinline__ uint32_t f2tf32(float x) {
  uint32_t u;
  asm("cvt.rna.tf32.f32 %0, %1;" : "=r"(u) : "f"(x));
  return u;
}
__device__ __forceinline__ void split_tf32(float x, uint32_t& hi, uint32_t& lo) {
  hi = f2tf32(x);
  lo = f2tf32(x - __uint_as_float(hi));
}
__device__ __forceinline__ void mma_tf32(float c[4], const uint32_t a[4], const uint32_t b[2]) {
  asm volatile(
      "mma.sync.aligned.m16n8k8.row.col.f32.tf32.tf32.f32 "
      "{%0,%1,%2,%3}, {%4,%5,%6,%7}, {%8,%9}, {%0,%1,%2,%3};"
      : "+f"(c[0]), "+f"(c[1]), "+f"(c[2]), "+f"(c[3])
      : "r"(a[0]), "r"(a[1]), "r"(a[2]), "r"(a[3]), "r"(b[0]), "r"(b[1]));
}

// ---------------- channel mix GEMM (3xTF32 tensor cores) + bilinear epilogue ----------------
// out[b][o][h][w] = sum_c W[o][c]*g_R[b][c][h][w] + bilinear_up(x_high)[b][o][h][w]
// Block: 256 thr = 8 warps, output tile 128(o) x 128(w) for fixed (b,h), K=256.
// Warp tile 32(o) x 64(w): warps arranged 4(o) x 2(w).
__global__ void __launch_bounds__(256) mix_kernel(const float* __restrict__ xh, float* __restrict__ out) {
  int b = blockIdx.z;
  int h = blockIdx.x;
  int oBase = blockIdx.y * 128;
  int tid = threadIdx.x;
  int warp = tid >> 5, lane = tid & 31;
  int lr = lane >> 2, lc = lane & 3;       // fragment row group / col group
  int warpO = (warp & 3) * 32;
  int warpW = (warp >> 2) * 64;

  __shared__ float As[32][132];  // [k][o]
  __shared__ float Bs[32][132];  // [k][w]
  const float* Rb = g_R + (size_t)b * 256 * 16384 + h * 128;

  float acc[2][8][4];
#pragma unroll
  for (int mt = 0; mt < 2; mt++)
#pragma unroll
    for (int nt = 0; nt < 8; nt++)
#pragma unroll
      for (int q = 0; q < 4; q++) acc[mt][nt][q] = 0.f;

  for (int kb = 0; kb < 256; kb += 32) {
    __syncthreads();
#pragma unroll
    for (int i = 0; i < 4; i++) {
      int idx = tid * 4 + i * 1024;   // 0..4095
      int krow = idx >> 7, col = idx & 127;
      *(float4*)&As[krow][col] = *(const float4*)&g_Wt[(kb + krow) * 256 + oBase + col];
      *(float4*)&Bs[krow][col] = *(const float4*)&Rb[(size_t)(kb + krow) * 16384 + col];
    }
    __syncthreads();
#pragma unroll
    for (int kk = 0; kk < 4; kk++) {
      int k0 = kk * 8;
      // A fragments (2 m-tiles), hi/lo split
      uint32_t ahi[2][4], alo[2][4];
#pragma unroll
      for (int mt = 0; mt < 2; mt++)
#pragma unroll
        for (int rg = 0; rg < 4; rg++) {
          int ko = k0 + lc + 4 * (rg >> 1);
          int mo = warpO + mt * 16 + lr + 8 * (rg & 1);
          split_tf32(As[ko][mo], ahi[mt][rg], alo[mt][rg]);
        }
#pragma unroll
      for (int nt = 0; nt < 8; nt++) {
        uint32_t bhi[2], blo[2];
#pragma unroll
        for (int rg = 0; rg < 2; rg++) {
          int ko = k0 + lc + 4 * rg;
          int no = warpW + nt * 8 + lr;
          split_tf32(Bs[ko][no], bhi[rg], blo[rg]);
        }
#pragma unroll
        for (int mt = 0; mt < 2; mt++) {
          mma_tf32(acc[mt][nt], ahi[mt], bhi);   // hi*hi
          mma_tf32(acc[mt][nt], ahi[mt], blo);   // hi*lo
          mma_tf32(acc[mt][nt], alo[mt], bhi);   // lo*hi
        }
      }
    }
  }

  // bilinear-upsample epilogue (jax.image.resize half-pixel, clamped edges)
  float hin = 0.5f * (float)h - 0.25f;
  int hi0 = hin < 0.f ? 0 : (int)hin;
  float hf = hin < 0.f ? 0.f : hin - (float)hi0;
  int hi1 = hi0 + 1 < 64 ? hi0 + 1 : 63;

#pragma unroll
  for (int mt = 0; mt < 2; mt++) {
#pragma unroll
    for (int half = 0; half < 2; half++) {
      int o = oBase + warpO + mt * 16 + lr + 8 * half;
      const float* xb = xh + (size_t)(b * 256 + o) * 4096;
      const float* r0 = xb + hi0 * 64;
      const float* r1 = xb + hi1 * 64;
      float* orow = out + (size_t)(b * 256 + o) * 16384 + h * 128;
#pragma unroll
      for (int nt = 0; nt < 8; nt++) {
        int w0 = warpW + nt * 8 + 2 * lc;
        float v[2];
#pragma unroll
        for (int j = 0; j < 2; j++) {
          int w = w0 + j;
          float win = 0.5f * (float)w - 0.25f;
          int wi0 = win < 0.f ? 0 : (int)win;
          float wf = win < 0.f ? 0.f : win - (float)wi0;
          int wi1 = wi0 + 1 < 64 ? wi0 + 1 : 63;
          float top = r0[wi0] * (1.f - wf) + r0[wi1] * wf;
          float bot = r1[wi0] * (1.f - wf) + r1[wi1] * wf;
          v[j] = acc[mt][nt][half * 2 + j] + top * (1.f - hf) + bot * hf;
        }
        *(float2*)&orow[w0] = make_float2(v[0], v[1]);
      }
    }
  }
}

// ---------------- launch ----------------
extern "C" void kernel_launch(void* const* d_in, const int* in_sizes, int n_in,
                              void* d_out, int out_size) {
  const float* x_high = (const float*)d_in[0];
  const float* x_low = (const float*)d_in[1];
  const float* w1 = (const float*)d_in[2];
  const float* b1 = (const float*)d_in[3];
  const float* w2 = (const float*)d_in[4];
  const float* b2 = (const float*)d_in[5];
  const float* refine_w = (const float*)d_in[6];
  float* out = (float*)d_out;

  const int SMEM_FFT = 2 * 128 * 129 * 4;  // 132096 B
  cudaFuncSetAttribute((const void*)fwd_fft_pair_kernel, cudaFuncAttributeMaxDynamicSharedMemorySize, SMEM_FFT);
  cudaFuncSetAttribute((const void*)inv_fft_pair_kernel, cudaFuncAttributeMaxDynamicSharedMemorySize, SMEM_FFT);

  transpose_w<<<dim3(8, 8), dim3(32, 32)>>>(refine_w);
  fwd_fft_pair_kernel<<<1024, 1024, SMEM_FFT>>>(x_low);
  mlp_kernel<<<8, 256>>>(w1, b1, w2, b2);
  conv_kernel<<<dim3(2048, 8), 256>>>();
  inv_fft_pair_kernel<<<1024, 1024, SMEM_FFT>>>();
  mix_kernel<<<dim3(128, 2, 8), 256>>>(x_high, out);
}

// round 8
// speedup vs baseline: 1.4606x; 1.1302x over previous
#include <cuda_runtime.h>
#include <cuda_bf16.h>
#include <math.h>
#include <stdint.h>

#ifndef M_PI
#define M_PI 3.14159265358979323846
#endif

#define FULLMASK 0xffffffffu

// ---------------- scratch (static device globals; no allocations) ----------------
__device__ float2   g_F[33554432];    // shifted FFT of x_low   (B*C,128,128) complex
__device__ float2   g_G[33554432];    // conv output            (B*C,128,128) complex
__device__ uint32_t g_Rhi[16777216];  // real(ifft2) bf16 hi, packed channel pairs [B*128][16384]
__device__ uint32_t g_Rlo[16777216];  // residual bf16 lo
__device__ float    g_kern[8 * 49];   // per-batch 7x7 kernel
__device__ uint32_t g_Whi[32768];     // refine_w split: [c2=128][o=256] {bf16(W[o][2c2]) | bf16(W[o][2c2+1])<<16}
__device__ uint32_t g_Wlo[32768];     // residuals

// ---------------- complex helpers ----------------
__device__ __forceinline__ float2 cadd(float2 a, float2 b) { return make_float2(a.x + b.x, a.y + b.y); }
__device__ __forceinline__ float2 csub(float2 a, float2 b) { return make_float2(a.x - b.x, a.y - b.y); }
__device__ __forceinline__ float2 cmul(float2 a, float2 b) {
  return make_float2(a.x * b.x - a.y * b.y, a.x * b.y + a.y * b.x);
}

// ---------------- bf16 split helpers ----------------
// pack: low 16 bits = bf16(xe) (even k), high 16 = bf16(xo) (odd k)
__device__ __forceinline__ void split2_bf16(float xe, float xo, uint32_t& hi, uint32_t& lo) {
  __nv_bfloat16 he = __float2bfloat16_rn(xe);
  __nv_bfloat16 ho = __float2bfloat16_rn(xo);
  float re = xe - __bfloat162float(he);
  float ro = xo - __bfloat162float(ho);
  __nv_bfloat16 le = __float2bfloat16_rn(re);
  __nv_bfloat16 lo16 = __float2bfloat16_rn(ro);
  hi = (uint32_t)__bfloat16_as_ushort(he) | ((uint32_t)__bfloat16_as_ushort(ho) << 16);
  lo = (uint32_t)__bfloat16_as_ushort(le) | ((uint32_t)__bfloat16_as_ushort(lo16) << 16);
}

// ---------------- warp-resident 128-pt DIF FFT ----------------
template<int SGN>
__device__ __forceinline__ void make_twiddles(int lane, float2 tw[7]) {
  const float TP = 6.283185307179586f * (float)SGN;
  float fr[7] = { lane / 128.f, (lane + 32) / 128.f, lane / 64.f,
                  (lane & 15) / 32.f, (lane & 7) / 16.f, (lane & 3) / 8.f, (lane & 1) / 4.f };
#pragma unroll
  for (int i = 0; i < 7; i++) {
    float s, c;
    sincosf(TP * fr[i], &s, &c);
    tw[i] = make_float2(c, s);
  }
}

__device__ __forceinline__ void fft128(float2 v[4], const float2 tw[7], int lane) {
  float2 t, u;
  t = v[0]; u = v[2]; v[0] = cadd(t, u); v[2] = cmul(csub(t, u), tw[0]);
  t = v[1]; u = v[3]; v[1] = cadd(t, u); v[3] = cmul(csub(t, u), tw[1]);
  t = v[0]; u = v[1]; v[0] = cadd(t, u); v[1] = cmul(csub(t, u), tw[2]);
  t = v[2]; u = v[3]; v[2] = cadd(t, u); v[3] = cmul(csub(t, u), tw[2]);
#pragma unroll
  for (int hi = 0; hi < 5; hi++) {
    int h = 16 >> hi;
    bool up = (lane & h) != 0;
#pragma unroll
    for (int s = 0; s < 4; s++) {
      float prx = __shfl_xor_sync(FULLMASK, v[s].x, h);
      float pry = __shfl_xor_sync(FULLMASK, v[s].y, h);
      float2 pr = make_float2(prx, pry);
      if (hi < 4) {
        v[s] = up ? cmul(csub(pr, v[s]), tw[3 + hi]) : cadd(v[s], pr);
      } else {
        v[s] = up ? csub(pr, v[s]) : cadd(v[s], pr);
      }
    }
  }
}

__device__ __forceinline__ int bitrev7(int p) { return (int)(__brev((unsigned)p) >> 25); }

// ---------------- forward FFT (channel-pair packed): x_low -> g_F ----------------
__global__ void __launch_bounds__(1024) fwd_fft_pair_kernel(const float* __restrict__ x) {
  extern __shared__ float sm[];
  float* sre = sm;
  float* sim = sm + 128 * 129;
  int pair = blockIdx.x;
  int ch1 = pair * 2, ch2 = ch1 + 1;
  int tid = threadIdx.x;
  int warp = tid >> 5, lane = tid & 31;
  float2 tw[7];
  make_twiddles<-1>(lane, tw);
  const float* x1 = x + (size_t)ch1 * 16384;
  const float* x2 = x + (size_t)ch2 * 16384;

  for (int r = warp; r < 128; r += 32) {
    float2 v[4];
#pragma unroll
    for (int s = 0; s < 4; s++) {
      int c = s * 32 + lane;
      v[s] = make_float2(x1[r * 128 + c] * 0.0078125f, x2[r * 128 + c] * 0.0078125f);
    }
    fft128(v, tw, lane);
#pragma unroll
    for (int s = 0; s < 4; s++) {
      int p = s * 32 + lane;
      int n = bitrev7(p) ^ 64;
      sre[r * 129 + n] = v[s].x;
      sim[r * 129 + n] = v[s].y;
    }
  }
  __syncthreads();
  for (int c = warp; c < 128; c += 32) {
    float2 v[4];
#pragma unroll
    for (int s = 0; s < 4; s++) {
      int p = s * 32 + lane;
      v[s] = make_float2(sre[p * 129 + c], sim[p * 129 + c]);
    }
    fft128(v, tw, lane);
#pragma unroll
    for (int s = 0; s < 4; s++) {
      int p = s * 32 + lane;
      int n = bitrev7(p) ^ 64;
      sre[n * 129 + c] = v[s].x;
      sim[n * 129 + c] = v[s].y;
    }
  }
  __syncthreads();
  float2* F1 = g_F + (size_t)ch1 * 16384;
  float2* F2 = g_F + (size_t)ch2 * 16384;
  for (int i = tid; i < 16384; i += 1024) {
    int r = i >> 7, c = i & 127;
    int mr = (128 - r) & 127, mc = (128 - c) & 127;
    float a = sre[r * 129 + c],  b = sim[r * 129 + c];
    float cc = sre[mr * 129 + mc], d = sim[mr * 129 + mc];
    F1[i] = make_float2((a + cc) * 0.5f, (b - d) * 0.5f);
    F2[i] = make_float2((b + d) * 0.5f, (cc - a) * 0.5f);
  }
}

// ---------------- tiny path: center magnitudes -> MLP -> anisotropic kernel ----------------
__global__ void __launch_bounds__(256) mlp_kernel(const float* __restrict__ w1, const float* __restrict__ b1,
                                                  const float* __restrict__ w2, const float* __restrict__ b2) {
  int b = blockIdx.x;
  int t = threadIdx.x;
  __shared__ float part[49][4];
  __shared__ float flat[49];
  __shared__ float hbuf[32];
  __shared__ float prm[3];
  __shared__ float kv[49];
  __shared__ float ksum;

  if (t < 196) {
    int p = t >> 2, q = t & 3;
    int i = p / 7, j = p % 7;
    const float2* Fp = g_F + ((size_t)b * 256) * 16384 + (61 + i) * 128 + (61 + j);
    float s = 0.f;
#pragma unroll 8
    for (int ch = q * 64; ch < q * 64 + 64; ch++) {
      float2 f = Fp[(size_t)ch * 16384];
      s += sqrtf(f.x * f.x + f.y * f.y);
    }
    part[p][q] = s;
  }
  __syncthreads();
  if (t < 49) flat[t] = (part[t][0] + part[t][1] + part[t][2] + part[t][3]) * (1.f / 256.f);
  __syncthreads();
  if (t < 32) {
    float a = b1[t];
#pragma unroll
    for (int i = 0; i < 49; i++) a += flat[i] * w1[t * 49 + i];
    hbuf[t] = fmaxf(a, 0.f);
  }
  __syncthreads();
  if (t < 3) {
    float a = b2[t];
#pragma unroll
    for (int u = 0; u < 32; u++) a += hbuf[u] * w2[t * 32 + u];
    prm[t] = a;
  }
  __syncthreads();
  if (t < 49) {
    float theta = atan2f(prm[0], prm[1]) * 0.5f + (float)M_PI * 0.5f;
    float lam1 = expf(prm[2]);
    float lam2 = 1.f / (lam1 + 1e-8f);
    float ct = cosf(theta), st = sinf(theta);
    int i = t / 7, j = t % 7;
    float yy = (float)(i - 3), xx = (float)(j - 3);
    float xr = xx * ct + yy * st;
    float yr = -xx * st + yy * ct;
    kv[t] = expf(-(xr * xr / (2.f * lam1 * lam1) + yr * yr / (2.f * lam2 * lam2)));
  }
  __syncthreads();
  if (t == 0) {
    float s = 0.f;
    for (int i = 0; i < 49; i++) s += kv[i];
    ksum = s;
  }
  __syncthreads();
  if (t < 49) g_kern[b * 49 + t] = kv[t] / (ksum + 1e-8f);
}

// ---------------- depthwise 7x7 correlation (zero pad) — R3 version (best measured) ----------------
__global__ void __launch_bounds__(256) conv_kernel() {
  __shared__ float2 tile[22][134];
  __shared__ float kc[49];
  int img = blockIdx.x;
  int b = img >> 8;
  int rBase = blockIdx.y * 16;
  int tid = threadIdx.x;
  if (tid < 49) kc[tid] = g_kern[b * 49 + tid];
  const float2* Fb = g_F + (size_t)img * 16384;
  for (int idx = tid; idx < 22 * 134; idx += 256) {
    int tr = idx / 134, tc = idx % 134;
    int gr = rBase - 3 + tr, gc = tc - 3;
    float2 val = make_float2(0.f, 0.f);
    if (gr >= 0 && gr < 128 && gc >= 0 && gc < 128) val = Fb[gr * 128 + gc];
    tile[tr][tc] = val;
  }
  __syncthreads();
  int w = tid & 127, rg = tid >> 7;
  float2* Gb = g_G + (size_t)img * 16384;
#pragma unroll
  for (int rr = 0; rr < 8; rr++) {
    int rl = rg * 8 + rr;
    float sre = 0.f, simv = 0.f;
#pragma unroll
    for (int dy = 0; dy < 7; dy++)
#pragma unroll
      for (int dx = 0; dx < 7; dx++) {
        float2 in = tile[rl + dy][w + dx];
        float k = kc[dy * 7 + dx];
        sre += in.x * k;
        simv += in.y * k;
      }
    Gb[(rBase + rl) * 128 + w] = make_float2(sre, simv);
  }
}

// ---------------- inverse FFT (Hermitian channel-pair): g_G -> g_Rhi/g_Rlo (bf16 split) ----------------
__global__ void __launch_bounds__(1024) inv_fft_pair_kernel() {
  extern __shared__ float sm[];
  float* sre = sm;
  float* sim = sm + 128 * 129;
  int pair = blockIdx.x;
  int ch1 = pair * 2, ch2 = ch1 + 1;
  int tid = threadIdx.x;
  int warp = tid >> 5, lane = tid & 31;
  float2 tw[7];
  make_twiddles<1>(lane, tw);
  const float2* G1 = g_G + (size_t)ch1 * 16384;
  const float2* G2 = g_G + (size_t)ch2 * 16384;

  for (int r = warp; r < 128; r += 32) {
    int mr = (128 - r) & 127;
    float2 v[4];
#pragma unroll
    for (int s = 0; s < 4; s++) {
      int cidx = (s * 32 + lane) ^ 64;
      int mc = (128 - cidx) & 127;
      float2 A1 = G1[r * 128 + cidx];
      float2 B1 = G1[mr * 128 + mc];
      float2 A2 = G2[r * 128 + cidx];
      float2 B2 = G2[mr * 128 + mc];
      v[s] = make_float2((A1.x + B1.x - A2.y + B2.y) * 0.00390625f,
                         (A1.y - B1.y + A2.x + B2.x) * 0.00390625f);
    }
    fft128(v, tw, lane);
#pragma unroll
    for (int s = 0; s < 4; s++) {
      int p = s * 32 + lane;
      int n = bitrev7(p);
      sre[r * 129 + n] = v[s].x;
      sim[r * 129 + n] = v[s].y;
    }
  }
  __syncthreads();
  for (int c = warp; c < 128; c += 32) {
    float2 v[4];
#pragma unroll
    for (int s = 0; s < 4; s++) {
      int ridx = (s * 32 + lane) ^ 64;
      v[s] = make_float2(sre[ridx * 129 + c], sim[ridx * 129 + c]);
    }
    fft128(v, tw, lane);
#pragma unroll
    for (int s = 0; s < 4; s++) {
      int p = s * 32 + lane;
      int n = bitrev7(p);
      sre[n * 129 + c] = v[s].x;
      sim[n * 129 + c] = v[s].y;
    }
  }
  __syncthreads();
  // r1 = sre (ch even), r2 = sim (ch odd) -> packed bf16 hi/lo along channel pairs
  uint32_t* Rh = g_Rhi + (size_t)pair * 16384;
  uint32_t* Rl = g_Rlo + (size_t)pair * 16384;
  for (int i = tid; i < 16384; i += 1024) {
    int r = i >> 7, c = i & 127;
    uint32_t hi, lo;
    split2_bf16(sre[r * 129 + c], sim[r * 129 + c], hi, lo);
    Rh[i] = hi;
    Rl[i] = lo;
  }
}

// ---------------- weight prep: refine_w -> bf16-split packed channel pairs ----------------
// g_Whi[c2*256+o] = {bf16(W[o][2c2]) , bf16(W[o][2c2+1])<<16}, g_Wlo = residuals
__global__ void __launch_bounds__(256) wsplit_kernel(const float* __restrict__ W) {
  int idx = blockIdx.x * 256 + threadIdx.x;   // 0..32767
  int c2 = idx & 127, o = idx >> 7;
  float xe = W[o * 256 + 2 * c2];
  float xo = W[o * 256 + 2 * c2 + 1];
  uint32_t hi, lo;
  split2_bf16(xe, xo, hi, lo);
  g_Whi[c2 * 256 + o] = hi;
  g_Wlo[c2 * 256 + o] = lo;
}

// ---------------- bf16 MMA helper ----------------
__device__ __forceinline__ void mma_bf16(float* c, uint32_t a0, uint32_t a1, uint32_t a2, uint32_t a3,
                                         uint32_t b0, uint32_t b1) {
  asm volatile(
      "mma.sync.aligned.m16n8k16.row.col.f32.bf16.bf16.f32 "
      "{%0,%1,%2,%3}, {%4,%5,%6,%7}, {%8,%9}, {%0,%1,%2,%3};"
      : "+f"(c[0]), "+f"(c[1]), "+f"(c[2]), "+f"(c[3])
      : "r"(a0), "r"(a1), "r"(a2), "r"(a3), "r"(b0), "r"(b1));
}

// ---------------- channel mix GEMM (3-term bf16 tensor cores) + bilinear epilogue ----------------
// Block: 256 thr = 8 warps; tile 128(o) x 128(w), K = 256 channels (128 k2-pairs).
// Warps 4(o) x 2(w); warp tile 32(o) x 64(w). smem [k2][o or w] of uint2{hi,lo}.
__global__ void __launch_bounds__(256, 2) mix_kernel(const float* __restrict__ xh, float* __restrict__ out) {
  int b = blockIdx.z;
  int h = blockIdx.x;
  int oBase = blockIdx.y * 128;
  int tid = threadIdx.x;
  int warp = tid >> 5, lane = tid & 31;
  int lr = lane >> 2, lc = lane & 3;
  int warpO = (warp & 3) * 32;
  int warpW = (warp >> 2) * 64;

  __shared__ uint2 As[16][136];  // [k2][o]  {hi,lo}; stride 136*8B -> conflict-free frag loads
  __shared__ uint2 Bs[16][136];  // [k2][w]

  float acc[2][8][4];
#pragma unroll
  for (int mt = 0; mt < 2; mt++)
#pragma unroll
    for (int nt = 0; nt < 8; nt++)
#pragma unroll
      for (int q = 0; q < 4; q++) acc[mt][nt][q] = 0.f;

  const uint32_t* RhB = g_Rhi + (size_t)b * 128 * 16384 + h * 128;
  const uint32_t* RlB = g_Rlo + (size_t)b * 128 * 16384 + h * 128;

  for (int kb = 0; kb < 8; kb++) {      // 8 x 16 k2 = 128 pairs = 256 channels
    __syncthreads();
#pragma unroll
    for (int it = 0; it < 4; it++) {
      int item = it * 256 + tid;        // 0..1023 (16 k2 x 64 o2)
      int o2 = item & 63;
      int k2 = item >> 6;
      uint2 ah = *(const uint2*)&g_Whi[(kb * 16 + k2) * 256 + oBase + o2 * 2];
      uint2 al = *(const uint2*)&g_Wlo[(kb * 16 + k2) * 256 + oBase + o2 * 2];
      *(uint4*)&As[k2][o2 * 2] = make_uint4(ah.x, al.x, ah.y, al.y);
      uint2 bh = *(const uint2*)&RhB[(size_t)(kb * 16 + k2) * 16384 + o2 * 2];
      uint2 bl = *(const uint2*)&RlB[(size_t)(kb * 16 + k2) * 16384 + o2 * 2];
      *(uint4*)&Bs[k2][o2 * 2] = make_uint4(bh.x, bl.x, bh.y, bl.y);
    }
    __syncthreads();
#pragma unroll
    for (int s = 0; s < 2; s++) {       // two k16 steps per staged block
      uint2 af[2][4];
#pragma unroll
      for (int mt = 0; mt < 2; mt++) {
#pragma unroll
        for (int rg = 0; rg < 4; rg++) {
          int k2 = s * 8 + lc + 4 * (rg >> 1);
          int o = warpO + mt * 16 + lr + 8 * (rg & 1);
          af[mt][rg] = As[k2][o];
        }
      }
      const uint2* bRow0 = &Bs[s * 8 + lc][warpW + lr];
      const uint2* bRow1 = &Bs[s * 8 + lc + 4][warpW + lr];
#pragma unroll
      for (int nt = 0; nt < 8; nt++) {
        uint2 b0 = bRow0[nt * 8];
        uint2 b1 = bRow1[nt * 8];
#pragma unroll
        for (int mt = 0; mt < 2; mt++) {
          mma_bf16(acc[mt][nt], af[mt][0].x, af[mt][1].x, af[mt][2].x, af[mt][3].x, b0.x, b1.x); // hi*hi
          mma_bf16(acc[mt][nt], af[mt][0].x, af[mt][1].x, af[mt][2].x, af[mt][3].x, b0.y, b1.y); // hi*lo
          mma_bf16(acc[mt][nt], af[mt][0].y, af[mt][1].y, af[mt][2].y, af[mt][3].y, b0.x, b1.x); // lo*hi
        }
      }
    }
  }

  // bilinear-upsample epilogue (jax.image.resize half-pixel, clamped edges)
  float hin = 0.5f * (float)h - 0.25f;
  int hi0 = hin < 0.f ? 0 : (int)hin;
  float hf = hin < 0.f ? 0.f : hin - (float)hi0;
  int hi1 = hi0 + 1 < 64 ? hi0 + 1 : 63;

#pragma unroll
  for (int mt = 0; mt < 2; mt++) {
#pragma unroll
    for (int half = 0; half < 2; half++) {
      int o = oBase + warpO + mt * 16 + lr + 8 * half;
      const float* xb = xh + (size_t)(b * 256 + o) * 4096;
      const float* r0 = xb + hi0 * 64;
      const float* r1 = xb + hi1 * 64;
      float* orow = out + (size_t)(b * 256 + o) * 16384 + h * 128;
#pragma unroll
      for (int nt = 0; nt < 8; nt++) {
        int w0 = warpW + nt * 8 + 2 * lc;
        float v[2];
#pragma unroll
        for (int j = 0; j < 2; j++) {
          int w = w0 + j;
          float win = 0.5f * (float)w - 0.25f;
          int wi0 = win < 0.f ? 0 : (int)win;
          float wf = win < 0.f ? 0.f : win - (float)wi0;
          int wi1 = wi0 + 1 < 64 ? wi0 + 1 : 63;
          float top = r0[wi0] * (1.f - wf) + r0[wi1] * wf;
          float bot = r1[wi0] * (1.f - wf) + r1[wi1] * wf;
          v[j] = acc[mt][nt][half * 2 + j] + top * (1.f - hf) + bot * hf;
        }
        *(float2*)&orow[w0] = make_float2(v[0], v[1]);
      }
    }
  }
}

// ---------------- launch ----------------
extern "C" void kernel_launch(void* const* d_in, const int* in_sizes, int n_in,
                              void* d_out, int out_size) {
  const float* x_high = (const float*)d_in[0];
  const float* x_low = (const float*)d_in[1];
  const float* w1 = (const float*)d_in[2];
  const float* b1 = (const float*)d_in[3];
  const float* w2 = (const float*)d_in[4];
  const float* b2 = (const float*)d_in[5];
  const float* refine_w = (const float*)d_in[6];
  float* out = (float*)d_out;

  const int SMEM_FFT = 2 * 128 * 129 * 4;  // 132096 B
  cudaFuncSetAttribute((const void*)fwd_fft_pair_kernel, cudaFuncAttributeMaxDynamicSharedMemorySize, SMEM_FFT);
  cudaFuncSetAttribute((const void*)inv_fft_pair_kernel, cudaFuncAttributeMaxDynamicSharedMemorySize, SMEM_FFT);

  wsplit_kernel<<<128, 256>>>(refine_w);
  fwd_fft_pair_kernel<<<1024, 1024, SMEM_FFT>>>(x_low);
  mlp_kernel<<<8, 256>>>(w1, b1, w2, b2);
  conv_kernel<<<dim3(2048, 8), 256>>>();
  inv_fft_pair_kernel<<<1024, 1024, SMEM_FFT>>>();
  mix_kernel<<<dim3(128, 2, 8), 256>>>(x_high, out);
}